// round 4
// baseline (speedup 1.0000x reference)
#include <cuda_runtime.h>

// qpNet: h = x @ W^T + b  (x: [B,5], W: [5,5], b: [5])
//        z = max(-h, -1000)   (closed-form separable QP solution, EPS=1e-3)
//
// Memory-bound streaming kernel. Each thread processes 4 rows (20 floats)
// via 5 aligned float4 loads + 5 float4 stores.

#define NROWS_PER_THREAD 4
#define THREADS 256

__global__ __launch_bounds__(THREADS)
void qpNet_kernel(const float4* __restrict__ x4,
                  const float*  __restrict__ W,
                  const float*  __restrict__ b,
                  float4*       __restrict__ out4,
                  int n_groups)
{
    int t = blockIdx.x * blockDim.x + threadIdx.x;
    if (t >= n_groups) return;

    // Broadcast weights/bias (warp-uniform, L1-resident)
    float w[25];
#pragma unroll
    for (int i = 0; i < 25; i++) w[i] = __ldg(W + i);
    float bb[5];
#pragma unroll
    for (int j = 0; j < 5; j++) bb[j] = __ldg(b + j);

    // 4 rows = 20 floats = 5 float4 (base 20*t floats is 16B-aligned)
    int base = t * 5;
    float4 f0 = x4[base + 0];
    float4 f1 = x4[base + 1];
    float4 f2 = x4[base + 2];
    float4 f3 = x4[base + 3];
    float4 f4 = x4[base + 4];

    float in[20] = {
        f0.x, f0.y, f0.z, f0.w,
        f1.x, f1.y, f1.z, f1.w,
        f2.x, f2.y, f2.z, f2.w,
        f3.x, f3.y, f3.z, f3.w,
        f4.x, f4.y, f4.z, f4.w
    };

    float o[20];
#pragma unroll
    for (int r = 0; r < NROWS_PER_THREAD; r++) {
#pragma unroll
        for (int j = 0; j < 5; j++) {
            float s = bb[j];
#pragma unroll
            for (int k = 0; k < 5; k++) {
                s = fmaf(in[r * 5 + k], w[j * 5 + k], s);
            }
            o[r * 5 + j] = fmaxf(-s, -1000.0f);
        }
    }

    float4 g0 = make_float4(o[0],  o[1],  o[2],  o[3]);
    float4 g1 = make_float4(o[4],  o[5],  o[6],  o[7]);
    float4 g2 = make_float4(o[8],  o[9],  o[10], o[11]);
    float4 g3 = make_float4(o[12], o[13], o[14], o[15]);
    float4 g4 = make_float4(o[16], o[17], o[18], o[19]);

    out4[base + 0] = g0;
    out4[base + 1] = g1;
    out4[base + 2] = g2;
    out4[base + 3] = g3;
    out4[base + 4] = g4;
}

extern "C" void kernel_launch(void* const* d_in, const int* in_sizes, int n_in,
                              void* d_out, int out_size)
{
    const float* x    = (const float*)d_in[0];   // [B, 5]
    const float* W    = (const float*)d_in[1];   // [5, 5]
    const float* b_fc = (const float*)d_in[2];   // [5]
    float* out = (float*)d_out;                  // [B, 5]

    int n_elems  = in_sizes[0];                  // B * 5
    int n_rows   = n_elems / 5;                  // B
    int n_groups = n_rows / NROWS_PER_THREAD;    // B/4 (B = 4194304, divisible)

    int blocks = (n_groups + THREADS - 1) / THREADS;
    qpNet_kernel<<<blocks, THREADS>>>(
        (const float4*)x, W, b_fc, (float4*)out, n_groups);
}